// round 12
// baseline (speedup 1.0000x reference)
#include <cuda_runtime.h>
#include <math.h>
#include <stdint.h>

#define TT   4096
#define HID  2048
#define NH   32
#define HD   128
#define PP   4096
#define TP   (TT * PP)
#define NQKV 12288    // 3*PP
#define NFAB 384      // fa(128) | ga(128) | beta(32 pad->128)

// ---------------- scratch (device globals; no allocations allowed) ----------
__device__ float g_hsr[TT * HID];
__device__ float g_qkvp[TT * NQKV];
__device__ float g_q [TP];
__device__ float g_k [TP];
__device__ float g_v [TP];
__device__ float g_eg[TP];
__device__ float g_g2[TP];
__device__ float g_o [TP];
__device__ float g_fab[TT * NFAB];
__device__ float g_beta[TT * NH];
__device__ float g_wqkvR[HID * NQKV];
__device__ float g_wfabR[HID * NFAB];
__device__ float g_wfbR[HD * PP];
__device__ float g_wgbR[HD * PP];
__device__ float g_woR[PP * HID];

// ---------------- helpers -----------------------------------------------------
__device__ __forceinline__ uint32_t smem_u32(const void* p) {
    uint32_t a;
    asm("{ .reg .u64 t; cvta.to.shared.u64 t, %1; cvt.u32.u64 %0, t; }" : "=r"(a) : "l"(p));
    return a;
}
__device__ __forceinline__ float rna_tf32(float x) {
    uint32_t o, i = __float_as_uint(x);
    asm("cvt.rna.tf32.f32 %0, %1;" : "=r"(o) : "r"(i));
    return __uint_as_float(o);
}
__device__ __forceinline__ void cp_async16(uint32_t dst, const float* src) {
    asm volatile("cp.async.cg.shared.global [%0], [%1], 16;\n"
                 :: "r"(dst), "l"(__cvta_generic_to_global(src)));
}
__device__ __forceinline__ void cp_async4(uint32_t dst, const float* src) {
    asm volatile("cp.async.ca.shared.global [%0], [%1], 4;\n"
                 :: "r"(dst), "l"(__cvta_generic_to_global(src)));
}
__device__ __forceinline__ void cp_commit() { asm volatile("cp.async.commit_group;\n" ::: "memory"); }

#define MMA_TF32(d, a, b)                                                      \
    asm volatile("mma.sync.aligned.m16n8k8.row.col.f32.tf32.tf32.f32 "        \
                 "{%0,%1,%2,%3}, {%4,%5,%6,%7}, {%8,%9}, {%0,%1,%2,%3};"      \
                 : "+f"((d)[0]), "+f"((d)[1]), "+f"((d)[2]), "+f"((d)[3])     \
                 : "r"((a)[0]), "r"((a)[1]), "r"((a)[2]), "r"((a)[3]),        \
                   "r"((b)[0]), "r"((b)[1]))

#define LDSM_X4(r, addr)                                                       \
    asm volatile("ldmatrix.sync.aligned.m8n8.x4.shared.b16 {%0,%1,%2,%3}, [%4];" \
                 : "=r"((r)[0]), "=r"((r)[1]), "=r"((r)[2]), "=r"((r)[3])      \
                 : "r"(addr))

// ---------------- tf32 mma.sync GEMM (R8/R10/R11 exact) ------------------------
#define BM 128
#define BN 128
#define BK 32
#define ASTR 36
#define BSTR 136
#define A_STAGE (BM * ASTR)
#define B_STAGE (BK * BSTR)
#define STAGE_F (A_STAGE + B_STAGE)
#define NSTAGE 3
#define GEMM_SMEM (NSTAGE * STAGE_F * 4)

__global__ __launch_bounds__(256, 2) void mma_gemm(const float* __restrict__ A, int lda,
                                                   const float* __restrict__ B, int ldb,
                                                   float* __restrict__ C, int ldc,
                                                   int Nvalid, int K, int round_limit) {
    extern __shared__ float sm[];
    const uint32_t sb = smem_u32(sm);

    const int tid = threadIdx.x;
    const int wid = tid >> 5, lane = tid & 31;
    const int g = lane >> 2, tig = lane & 3;
    const int wm = (wid & 1) * 64, wn = (wid >> 1) * 32;
    const int bm = blockIdx.y * BM, bn = blockIdx.x * BN;
    const int NC = K >> 5;

    const int arow = tid >> 3, akq = tid & 7;
    const int brow = tid >> 5, bnq = tid & 31;
    const int aoff = (wm + (lane & 7) + ((lane >> 3) & 1) * 8) * ASTR + (lane >> 4) * 4;

    float acc[4][4][4];
#pragma unroll
    for (int i = 0; i < 4; i++)
#pragma unroll
        for (int j = 0; j < 4; j++)
#pragma unroll
            for (int r = 0; r < 4; r++) acc[i][j][r] = 0.f;

#define LOADST(chunk, stage) do {                                               \
        const int kb = (chunk) * BK;                                            \
        const uint32_t sA = sb + (stage) * STAGE_F * 4;                         \
        const uint32_t sB = sA + A_STAGE * 4;                                   \
        _Pragma("unroll")                                                       \
        for (int j = 0; j < 4; j++) {                                           \
            const int r = arow + 32 * j;                                        \
            cp_async16(sA + (r * ASTR + akq * 4) * 4,                           \
                       A + (size_t)(bm + r) * lda + kb + akq * 4);              \
        }                                                                       \
        _Pragma("unroll")                                                       \
        for (int j = 0; j < 4; j++) {                                           \
            const int r = brow + 8 * j;                                         \
            cp_async16(sB + (r * BSTR + bnq * 4) * 4,                           \
                       B + (size_t)(kb + r) * ldb + bn + bnq * 4);              \
        }                                                                       \
        cp_commit();                                                            \
    } while (0)

    LOADST(0, 0);
    if (NC > 1) LOADST(1, 1);

    for (int i = 0; i < NC; i++) {
        if (i + 2 < NC) asm volatile("cp.async.wait_group 1;\n" ::: "memory");
        else            asm volatile("cp.async.wait_group 0;\n" ::: "memory");
        __syncthreads();
        if (i + 2 < NC) {
            int st = i + 2;
            st = st - (st / NSTAGE) * NSTAGE;
            LOADST(i + 2, st);
        }

        const int stage = i - (i / NSTAGE) * NSTAGE;
        const uint32_t aBase = sb + stage * (STAGE_F * 4);
        const float* bb = sm + stage * STAGE_F + A_STAGE;
#pragma unroll
        for (int s = 0; s < 4; s++) {
            uint32_t af[4][4], bf[4][2];
            const int kk = 8 * s + tig;
#pragma unroll
            for (int mf = 0; mf < 4; mf++)
                LDSM_X4(af[mf], aBase + (uint32_t)(aoff + mf * (16 * ASTR) + 8 * s) * 4);
            const float* brow0 = bb + kk * BSTR + wn;
#pragma unroll
            for (int nf = 0; nf < 4; nf++) {
                bf[nf][0] = __float_as_uint(brow0[8 * nf + g]);
                bf[nf][1] = __float_as_uint(brow0[8 * nf + g + 4 * BSTR]);
            }
#pragma unroll
            for (int mf = 0; mf < 4; mf++)
#pragma unroll
                for (int nf = 0; nf < 4; nf++)
                    MMA_TF32(acc[mf][nf], af[mf], bf[nf]);
        }
    }

#pragma unroll
    for (int mf = 0; mf < 4; mf++) {
        const int row0 = bm + wm + 16 * mf + g;
#pragma unroll
        for (int nf = 0; nf < 4; nf++) {
            const int col = bn + wn + 8 * nf + 2 * tig;
            if (col < Nvalid) {
                float4 vals = make_float4(acc[mf][nf][0], acc[mf][nf][1],
                                          acc[mf][nf][2], acc[mf][nf][3]);
                if (col < round_limit) {
                    vals.x = rna_tf32(vals.x); vals.y = rna_tf32(vals.y);
                    vals.z = rna_tf32(vals.z); vals.w = rna_tf32(vals.w);
                }
                *reinterpret_cast<float2*>(C + (size_t)row0 * ldc + col) =
                    make_float2(vals.x, vals.y);
                *reinterpret_cast<float2*>(C + (size_t)(row0 + 8) * ldc + col) =
                    make_float2(vals.z, vals.w);
            }
        }
    }
}

// ---------------- prep kernels (R8/R11 exact) -----------------------------------
__global__ void prep_w4(const float4* __restrict__ in, float4* __restrict__ out, int n4) {
    const int i = blockIdx.x * 256 + threadIdx.x;
    if (i >= n4) return;
    float4 v = in[i];
    v.x = rna_tf32(v.x); v.y = rna_tf32(v.y);
    v.z = rna_tf32(v.z); v.w = rna_tf32(v.w);
    out[i] = v;
}

__global__ void prep_wqkv(const float4* __restrict__ wq, const float4* __restrict__ wk,
                          const float4* __restrict__ wv, float4* __restrict__ out, int total4) {
    const int i = blockIdx.x * 256 + threadIdx.x;
    if (i >= total4) return;
    const int n4 = i % (NQKV / 4);
    const int row = i / (NQKV / 4);
    const int seg = n4 >> 10;
    const int off = row * (PP / 4) + (n4 & 1023);
    float4 v = (seg == 0) ? wq[off] : (seg == 1) ? wk[off] : wv[off];
    v.x = rna_tf32(v.x); v.y = rna_tf32(v.y);
    v.z = rna_tf32(v.z); v.w = rna_tf32(v.w);
    out[i] = v;
}

__global__ void prep_wfab(const float4* __restrict__ wfa, const float4* __restrict__ wga,
                          const float4* __restrict__ wb, float4* __restrict__ out, int total4) {
    const int i = blockIdx.x * 256 + threadIdx.x;
    if (i >= total4) return;
    const int n4 = i % (NFAB / 4);
    const int row = i / (NFAB / 4);
    float4 v = make_float4(0.f, 0.f, 0.f, 0.f);
    if (n4 < 32)       v = wfa[row * 32 + n4];
    else if (n4 < 64)  v = wga[row * 32 + (n4 - 32)];
    else if (n4 < 72)  v = wb[row * 8 + (n4 - 64)];
    v.x = rna_tf32(v.x); v.y = rna_tf32(v.y);
    v.z = rna_tf32(v.z); v.w = rna_tf32(v.w);
    out[i] = v;
}

// ---------------- conv / beta / gate (R8/R11 exact) -----------------------------
__global__ __launch_bounds__(256) void conv_silu_k(const float* __restrict__ x,
                                                   const float* __restrict__ w,
                                                   float* __restrict__ y, float scale) {
    const int idx = blockIdx.x * 256 + threadIdx.x;
    const int t = idx >> 12;
    const int p = idx & (PP - 1);
    const size_t xi = (size_t)t * NQKV + p;
    const float4 wv = *reinterpret_cast<const float4*>(w + p * 4);
    float acc = x[xi] * wv.w;
    if (t >= 1) acc += x[xi - NQKV] * wv.z;
    if (t >= 2) acc += x[xi - 2 * NQKV] * wv.y;
    if (t >= 3) acc += x[xi - 3 * NQKV] * wv.x;
    const float sg = 1.f / (1.f + expf(-acc));
    y[idx] = acc * sg * scale;
}

__global__ void beta_k(const float* __restrict__ fab, float* __restrict__ b) {
    const int idx = blockIdx.x * 256 + threadIdx.x;
    if (idx >= TT * NH) return;
    const int t = idx >> 5, h = idx & 31;
    const float x = fab[(size_t)t * NFAB + 256 + h];
    b[idx] = 2.f / (1.f + expf(-x));
}

__global__ __launch_bounds__(256) void gate_k(float* __restrict__ g,
                                              const float* __restrict__ dt_bias,
                                              const float* __restrict__ A_log) {
    const int idx = blockIdx.x * 256 + threadIdx.x;
    const int p = idx & (PP - 1);
    const int h = p >> 7;
    const float a = expf(A_log[h]);
    const float x = g[idx] + dt_bias[p];
    const float sg = 1.f / (1.f + expf(-a * x));
    g[idx] = expf(-5.f * sg);
}

// ---------------- KDA scan v5: 4 columns/warp, 8-lane reductions ---------------
// CTA = (jblock, head), 256 threads: warp w owns columns 4w..4w+3.
// lane: group g = lane>>3 -> column 4w+g; s = lane&7 -> state els [16s..16s+15].
// k/q/e LDS are broadcast across groups; reductions are 3 shfl for 4 columns.
#define SBLK 8
#define SLOT_F 420                // k128|q128|e128|v32|beta1|pad3
#define BUF_F (SBLK * SLOT_F)
#define SNBUF 3
#define NBLK (TT / SBLK)

__global__ __launch_bounds__(256) void scan_k(const float* __restrict__ q,
                                              const float* __restrict__ k,
                                              const float* __restrict__ v,
                                              const float* __restrict__ eg,
                                              const float* __restrict__ beta,
                                              float* __restrict__ o) {
    __shared__ float ring[SNBUF * BUF_F];   // 40.3KB

    const int tid = threadIdx.x;
    const int h = blockIdx.y;
    const int jb = blockIdx.x;              // 0..3
    const int w = tid >> 5;                 // warp 0..7
    const int lane = tid & 31;
    const int grp = lane >> 3;              // 0..3 -> column within warp
    const int s = lane & 7;                 // state slice (0..7), 16 els each
    const int colL = w * 4 + grp;           // 0..31 local column
    const int off_v = h * HD + jb * 32 + colL;
    const uint32_t ring_u32 = smem_u32(ring);

    const float* kqe_base[3] = {k + h * HD, q + h * HD, eg + h * HD};

#define SCAN_FILL(blk) do {                                                     \
        const int t0 = (blk) * SBLK;                                            \
        const uint32_t bufb = ring_u32 + ((blk) % SNBUF) * (BUF_F * 4);         \
        for (int u = tid; u < SBLK * 104; u += 256) {                           \
            const int st = u / 104;                                             \
            const int item = u - st * 104;                                      \
            const size_t gbase = (size_t)(t0 + st) * PP;                        \
            const float* src;                                                   \
            if (item < 96) src = kqe_base[item >> 5] + gbase + (item & 31) * 4; \
            else           src = v + gbase + h * HD + jb * 32 + (item - 96) * 4;\
            cp_async16(bufb + (st * SLOT_F + item * 4) * 4, src);               \
        }                                                                       \
        if (tid < SBLK)                                                         \
            cp_async4(bufb + (tid * SLOT_F + 416) * 4,                          \
                      beta + (size_t)(t0 + tid) * NH + h);                      \
        cp_commit();                                                            \
    } while (0)

    float S[16];
#pragma unroll
    for (int r = 0; r < 16; r++) S[r] = 0.f;

    SCAN_FILL(0);
    SCAN_FILL(1);

    for (int b = 0; b < NBLK; b++) {
        if (b < NBLK - 1) asm volatile("cp.async.wait_group 1;\n" ::: "memory");
        else              asm volatile("cp.async.wait_group 0;\n" ::: "memory");
        __syncthreads();
        if (b + 2 < NBLK) SCAN_FILL(b + 2);

        const float* buf = ring + (b % SNBUF) * BUF_F;
#pragma unroll
        for (int si = 0; si < SBLK; si++) {
            const float* slot = buf + si * SLOT_F;
            float kf[16], qf[16], ef[16];
#pragma unroll
            for (int r = 0; r < 16; r += 4) {
                float4 kv4 = *reinterpret_cast<const float4*>(slot + s * 16 + r);
                float4 ev4 = *reinterpret_cast<const float4*>(slot + 256 + s * 16 + r);
                float4 qv4 = *reinterpret_cast<const float4*>(slot + 128 + s * 16 + r);
                kf[r] = kv4.x; kf[r+1] = kv4.y; kf[r+2] = kv4.z; kf[r+3] = kv4.w;
                ef[r] = ev4.x; ef[r+1] = ev4.y; ef[r+2] = ev4.z; ef[r+3] = ev4.w;
                qf[r] = qv4.x; qf[r+1] = qv4.y; qf[r+2] = qv4.z; qf[r+3] = qv4.w;
            }
            const float vt = slot[384 + colL];   // broadcast within 8-lane group
            const float bt = slot[416];

            float p0 = 0.f, p1 = 0.f;
#pragma unroll
            for (int r = 0; r < 16; r += 2) {
                S[r]     *= ef[r];     p0 += S[r]     * kf[r];
                S[r + 1] *= ef[r + 1]; p1 += S[r + 1] * kf[r + 1];
            }
            float part = p0 + p1;
            part += __shfl_xor_sync(0xffffffffu, part, 1);
            part += __shfl_xor_sync(0xffffffffu, part, 2);
            part += __shfl_xor_sync(0xffffffffu, part, 4);
            const float u = bt * (vt - part);
            float o0 = 0.f, o1 = 0.f;
#pragma unroll
            for (int r = 0; r < 16; r += 2) {
                S[r]     += kf[r] * u;     o0 += qf[r]     * S[r];
                S[r + 1] += kf[r + 1] * u; o1 += qf[r + 1] * S[r + 1];
            }
            float po = o0 + o1;
            po += __shfl_xor_sync(0xffffffffu, po, 1);
            po += __shfl_xor_sync(0xffffffffu, po, 2);
            po += __shfl_xor_sync(0xffffffffu, po, 4);
            if (s == 0) o[(size_t)(b * SBLK + si) * PP + off_v] = po;
        }
        __syncthreads();
    }
}

// ---------------- gated RMSNorm (R8/R11 exact) ----------------------------------
__global__ __launch_bounds__(256) void rmsnorm_k(float* __restrict__ o,
                                                 const float* __restrict__ g2,
                                                 const float* __restrict__ w) {
    const int warp = (blockIdx.x * blockDim.x + threadIdx.x) >> 5;
    const int lane = threadIdx.x & 31;
    if (warp >= TT * NH) return;
    const int base = warp * HD + lane * 4;
    float4 x = *reinterpret_cast<const float4*>(o + base);
    float ss = x.x * x.x + x.y * x.y + x.z * x.z + x.w * x.w;
#pragma unroll
    for (int d = 16; d > 0; d >>= 1) ss += __shfl_xor_sync(0xffffffffu, ss, d);
    const float rstd = rsqrtf(ss * (1.f / 128.f) + 1e-5f);
    const float4 g = *reinterpret_cast<const float4*>(g2 + base);
    const float4 wv = *reinterpret_cast<const float4*>(w + lane * 4);
    float4 r;
    r.x = rna_tf32(x.x * rstd * wv.x / (1.f + expf(-g.x)));
    r.y = rna_tf32(x.y * rstd * wv.y / (1.f + expf(-g.y)));
    r.z = rna_tf32(x.z * rstd * wv.z / (1.f + expf(-g.z)));
    r.w = rna_tf32(x.w * rstd * wv.w / (1.f + expf(-g.w)));
    *reinterpret_cast<float4*>(o + base) = r;
}

// ---------------- launch --------------------------------------------------------
extern "C" void kernel_launch(void* const* d_in, const int* in_sizes, int n_in,
                              void* d_out, int out_size) {
    const float* hs   = (const float*)d_in[0];
    const float* Wq   = (const float*)d_in[1];
    const float* Wk   = (const float*)d_in[2];
    const float* Wv   = (const float*)d_in[3];
    const float* cq   = (const float*)d_in[4];
    const float* ck   = (const float*)d_in[5];
    const float* cv   = (const float*)d_in[6];
    const float* Wb   = (const float*)d_in[7];
    const float* Wfa  = (const float*)d_in[8];
    const float* Wfb  = (const float*)d_in[9];
    const float* dtb  = (const float*)d_in[10];
    const float* Alog = (const float*)d_in[11];
    const float* Wga  = (const float*)d_in[12];
    const float* Wgb  = (const float*)d_in[13];
    const float* onw  = (const float*)d_in[14];
    const float* Wo   = (const float*)d_in[15];
    float* out = (float*)d_out;

    float *hsr, *qkvp, *q, *k, *v, *eg, *g2, *o, *fab, *beta;
    float *wqkvR, *wfabR, *wfbR, *wgbR, *woR;
    cudaGetSymbolAddress((void**)&hsr, g_hsr);
    cudaGetSymbolAddress((void**)&qkvp, g_qkvp);
    cudaGetSymbolAddress((void**)&q,  g_q);
    cudaGetSymbolAddress((void**)&k,  g_k);
    cudaGetSymbolAddress((void**)&v,  g_v);
    cudaGetSymbolAddress((void**)&eg, g_eg);
    cudaGetSymbolAddress((void**)&g2, g_g2);
    cudaGetSymbolAddress((void**)&o,  g_o);
    cudaGetSymbolAddress((void**)&fab, g_fab);
    cudaGetSymbolAddress((void**)&beta, g_beta);
    cudaGetSymbolAddress((void**)&wqkvR, g_wqkvR);
    cudaGetSymbolAddress((void**)&wfabR, g_wfabR);
    cudaGetSymbolAddress((void**)&wfbR, g_wfbR);
    cudaGetSymbolAddress((void**)&wgbR, g_wgbR);
    cudaGetSymbolAddress((void**)&woR, g_woR);

    cudaFuncSetAttribute(mma_gemm, cudaFuncAttributeMaxDynamicSharedMemorySize, GEMM_SMEM);

    const dim3 blk(256);

    // preps
    prep_w4<<<(TT * HID / 4 + 255) / 256, blk>>>((const float4*)hs, (float4*)hsr, TT * HID / 4);
    prep_wqkv<<<(HID * NQKV / 4 + 255) / 256, blk>>>((const float4*)Wq, (const float4*)Wk,
                                                     (const float4*)Wv, (float4*)wqkvR,
                                                     HID * NQKV / 4);
    prep_wfab<<<(HID * NFAB / 4 + 255) / 256, blk>>>((const float4*)Wfa, (const float4*)Wga,
                                                     (const float4*)Wb, (float4*)wfabR,
                                                     HID * NFAB / 4);

    // GEMMs
    mma_gemm<<<dim3(48, 32), blk, GEMM_SMEM>>>(hsr, HID, wqkvR, NQKV, qkvp, NQKV,
                                               NQKV / 2, HID, 0);
    mma_gemm<<<dim3(48, 32), blk, GEMM_SMEM>>>(hsr, HID, wqkvR + NQKV / 2, NQKV,
                                               qkvp + NQKV / 2, NQKV, NQKV / 2, HID, 0);
    mma_gemm<<<dim3(3, 32), blk, GEMM_SMEM>>>(hsr, HID, wfabR, NFAB, fab, NFAB,
                                              288, HID, 256);

    // convs + beta
    conv_silu_k<<<TP / 256, blk>>>(qkvp,          cq, q, 0.08838834764831845f);
    conv_silu_k<<<TP / 256, blk>>>(qkvp + PP,     ck, k, 1.f);
    conv_silu_k<<<TP / 256, blk>>>(qkvp + 2 * PP, cv, v, 1.f);
    beta_k<<<(TT * NH + 255) / 256, blk>>>(fab, beta);

    // gate GEMMs
    prep_w4<<<(HD * PP / 4 + 255) / 256, blk>>>((const float4*)Wfb, (float4*)wfbR, HD * PP / 4);
    mma_gemm<<<dim3(32, 32), blk, GEMM_SMEM>>>(fab, NFAB, wfbR, PP, eg, PP, PP, HD, 0);
    gate_k<<<TP / 256, blk>>>(eg, dtb, Alog);
    prep_w4<<<(HD * PP / 4 + 255) / 256, blk>>>((const float4*)Wgb, (float4*)wgbR, HD * PP / 4);
    mma_gemm<<<dim3(32, 32), blk, GEMM_SMEM>>>(fab + 128, NFAB, wgbR, PP, g2, PP, PP, HD, 0);

    // sequential KDA scan (v5: 4 columns/warp, 8-lane reductions)
    scan_k<<<dim3(4, NH), blk>>>(q, k, v, eg, beta, o);

    // gated rmsnorm + output projection
    rmsnorm_k<<<(TT * NH * 32) / 256, blk>>>(o, g2, onw);
    prep_w4<<<(PP * HID / 4 + 255) / 256, blk>>>((const float4*)Wo, (float4*)woR, PP * HID / 4);
    mma_gemm<<<dim3(16, 32), blk, GEMM_SMEM>>>(o, PP, woR, HID, out, HID, HID, PP, 0);
}

// round 13
// speedup vs baseline: 1.4109x; 1.4109x over previous
#include <cuda_runtime.h>
#include <math.h>
#include <stdint.h>

#define TT   4096
#define HID  2048
#define NH   32
#define HD   128
#define PP   4096
#define TP   (TT * PP)
#define NQKV 12288    // 3*PP
#define NFAB 384      // fa(128) | ga(128) | beta(32 pad->128)

// ---------------- scratch (device globals; no allocations allowed) ----------
__device__ float g_hsr[TT * HID];
__device__ float g_qkvp[TT * NQKV];
__device__ float g_q [TP];
__device__ float g_k [TP];
__device__ float g_v [TP];
__device__ float g_eg[TP];
__device__ float g_g2[TP];
__device__ float g_o [TP];
__device__ float g_fab[TT * NFAB];
__device__ float g_beta[TT * NH];
__device__ float g_wqkvR[HID * NQKV];
__device__ float g_wfabR[HID * NFAB];
__device__ float g_wfbR[HD * PP];
__device__ float g_wgbR[HD * PP];
__device__ float g_woR[PP * HID];

// ---------------- helpers -----------------------------------------------------
__device__ __forceinline__ uint32_t smem_u32(const void* p) {
    uint32_t a;
    asm("{ .reg .u64 t; cvta.to.shared.u64 t, %1; cvt.u32.u64 %0, t; }" : "=r"(a) : "l"(p));
    return a;
}
__device__ __forceinline__ float rna_tf32(float x) {
    uint32_t o, i = __float_as_uint(x);
    asm("cvt.rna.tf32.f32 %0, %1;" : "=r"(o) : "r"(i));
    return __uint_as_float(o);
}
__device__ __forceinline__ void cp_async16(uint32_t dst, const float* src) {
    asm volatile("cp.async.cg.shared.global [%0], [%1], 16;\n"
                 :: "r"(dst), "l"(__cvta_generic_to_global(src)));
}
__device__ __forceinline__ void cp_async4(uint32_t dst, const float* src) {
    asm volatile("cp.async.ca.shared.global [%0], [%1], 4;\n"
                 :: "r"(dst), "l"(__cvta_generic_to_global(src)));
}
__device__ __forceinline__ void cp_commit() { asm volatile("cp.async.commit_group;\n" ::: "memory"); }

#define MMA_TF32(d, a, b)                                                      \
    asm volatile("mma.sync.aligned.m16n8k8.row.col.f32.tf32.tf32.f32 "        \
                 "{%0,%1,%2,%3}, {%4,%5,%6,%7}, {%8,%9}, {%0,%1,%2,%3};"      \
                 : "+f"((d)[0]), "+f"((d)[1]), "+f"((d)[2]), "+f"((d)[3])     \
                 : "r"((a)[0]), "r"((a)[1]), "r"((a)[2]), "r"((a)[3]),        \
                   "r"((b)[0]), "r"((b)[1]))

#define LDSM_X4(r, addr)                                                       \
    asm volatile("ldmatrix.sync.aligned.m8n8.x4.shared.b16 {%0,%1,%2,%3}, [%4];" \
                 : "=r"((r)[0]), "=r"((r)[1]), "=r"((r)[2]), "=r"((r)[3])      \
                 : "r"(addr))

// packed f32x2 ops (base sm_100+ PTX)
typedef unsigned long long u64t;
#define FMA2(d, a, b, c) asm("fma.rn.f32x2 %0, %1, %2, %3;" : "=l"(d) : "l"(a), "l"(b), "l"(c))
#define MUL2(d, a, b)    asm("mul.rn.f32x2 %0, %1, %2;"     : "=l"(d) : "l"(a), "l"(b))
__device__ __forceinline__ u64t pk2(float lo, float hi) {
    u64t r; asm("mov.b64 %0, {%1, %2};" : "=l"(r) : "f"(lo), "f"(hi)); return r;
}
__device__ __forceinline__ void upk2(float& lo, float& hi, u64t v) {
    asm("mov.b64 {%0, %1}, %2;" : "=f"(lo), "=f"(hi) : "l"(v));
}

// ---------------- tf32 mma.sync GEMM (R8/R11 exact) ----------------------------
#define BM 128
#define BN 128
#define BK 32
#define ASTR 36
#define BSTR 136
#define A_STAGE (BM * ASTR)
#define B_STAGE (BK * BSTR)
#define STAGE_F (A_STAGE + B_STAGE)
#define NSTAGE 3
#define GEMM_SMEM (NSTAGE * STAGE_F * 4)

__global__ __launch_bounds__(256, 2) void mma_gemm(const float* __restrict__ A, int lda,
                                                   const float* __restrict__ B, int ldb,
                                                   float* __restrict__ C, int ldc,
                                                   int Nvalid, int K, int round_limit) {
    extern __shared__ float sm[];
    const uint32_t sb = smem_u32(sm);

    const int tid = threadIdx.x;
    const int wid = tid >> 5, lane = tid & 31;
    const int g = lane >> 2, tig = lane & 3;
    const int wm = (wid & 1) * 64, wn = (wid >> 1) * 32;
    const int bm = blockIdx.y * BM, bn = blockIdx.x * BN;
    const int NC = K >> 5;

    const int arow = tid >> 3, akq = tid & 7;
    const int brow = tid >> 5, bnq = tid & 31;
    const int aoff = (wm + (lane & 7) + ((lane >> 3) & 1) * 8) * ASTR + (lane >> 4) * 4;

    float acc[4][4][4];
#pragma unroll
    for (int i = 0; i < 4; i++)
#pragma unroll
        for (int j = 0; j < 4; j++)
#pragma unroll
            for (int r = 0; r < 4; r++) acc[i][j][r] = 0.f;

#define LOADST(chunk, stage) do {                                               \
        const int kb = (chunk) * BK;                                            \
        const uint32_t sA = sb + (stage) * STAGE_F * 4;                         \
        const uint32_t sB = sA + A_STAGE * 4;                                   \
        _Pragma("unroll")                                                       \
        for (int j = 0; j < 4; j++) {                                           \
            const int r = arow + 32 * j;                                        \
            cp_async16(sA + (r * ASTR + akq * 4) * 4,                           \
                       A + (size_t)(bm + r) * lda + kb + akq * 4);              \
        }                                                                       \
        _Pragma("unroll")                                                       \
        for (int j = 0; j < 4; j++) {                                           \
            const int r = brow + 8 * j;                                         \
            cp_async16(sB + (r * BSTR + bnq * 4) * 4,                           \
                       B + (size_t)(kb + r) * ldb + bn + bnq * 4);              \
        }                                                                       \
        cp_commit();                                                            \
    } while (0)

    LOADST(0, 0);
    if (NC > 1) LOADST(1, 1);

    for (int i = 0; i < NC; i++) {
        if (i + 2 < NC) asm volatile("cp.async.wait_group 1;\n" ::: "memory");
        else            asm volatile("cp.async.wait_group 0;\n" ::: "memory");
        __syncthreads();
        if (i + 2 < NC) {
            int st = i + 2;
            st = st - (st / NSTAGE) * NSTAGE;
            LOADST(i + 2, st);
        }

        const int stage = i - (i / NSTAGE) * NSTAGE;
        const uint32_t aBase = sb + stage * (STAGE_F * 4);
        const float* bb = sm + stage * STAGE_F + A_STAGE;
#pragma unroll
        for (int s = 0; s < 4; s++) {
            uint32_t af[4][4], bf[4][2];
            const int kk = 8 * s + tig;
#pragma unroll
            for (int mf = 0; mf < 4; mf++)
                LDSM_X4(af[mf], aBase + (uint32_t)(aoff + mf * (16 * ASTR) + 8 * s) * 4);
            const float* brow0 = bb + kk * BSTR + wn;
#pragma unroll
            for (int nf = 0; nf < 4; nf++) {
                bf[nf][0] = __float_as_uint(brow0[8 * nf + g]);
                bf[nf][1] = __float_as_uint(brow0[8 * nf + g + 4 * BSTR]);
            }
#pragma unroll
            for (int mf = 0; mf < 4; mf++)
#pragma unroll
                for (int nf = 0; nf < 4; nf++)
                    MMA_TF32(acc[mf][nf], af[mf], bf[nf]);
        }
    }

#pragma unroll
    for (int mf = 0; mf < 4; mf++) {
        const int row0 = bm + wm + 16 * mf + g;
#pragma unroll
        for (int nf = 0; nf < 4; nf++) {
            const int col = bn + wn + 8 * nf + 2 * tig;
            if (col < Nvalid) {
                float4 vals = make_float4(acc[mf][nf][0], acc[mf][nf][1],
                                          acc[mf][nf][2], acc[mf][nf][3]);
                if (col < round_limit) {
                    vals.x = rna_tf32(vals.x); vals.y = rna_tf32(vals.y);
                    vals.z = rna_tf32(vals.z); vals.w = rna_tf32(vals.w);
                }
                *reinterpret_cast<float2*>(C + (size_t)row0 * ldc + col) =
                    make_float2(vals.x, vals.y);
                *reinterpret_cast<float2*>(C + (size_t)(row0 + 8) * ldc + col) =
                    make_float2(vals.z, vals.w);
            }
        }
    }
}

// ---------------- prep kernels (R11 exact) --------------------------------------
__global__ void prep_w4(const float4* __restrict__ in, float4* __restrict__ out, int n4) {
    const int i = blockIdx.x * 256 + threadIdx.x;
    if (i >= n4) return;
    float4 v = in[i];
    v.x = rna_tf32(v.x); v.y = rna_tf32(v.y);
    v.z = rna_tf32(v.z); v.w = rna_tf32(v.w);
    out[i] = v;
}

__global__ void prep_wqkv(const float4* __restrict__ wq, const float4* __restrict__ wk,
                          const float4* __restrict__ wv, float4* __restrict__ out, int total4) {
    const int i = blockIdx.x * 256 + threadIdx.x;
    if (i >= total4) return;
    const int n4 = i % (NQKV / 4);
    const int row = i / (NQKV / 4);
    const int seg = n4 >> 10;
    const int off = row * (PP / 4) + (n4 & 1023);
    float4 v = (seg == 0) ? wq[off] : (seg == 1) ? wk[off] : wv[off];
    v.x = rna_tf32(v.x); v.y = rna_tf32(v.y);
    v.z = rna_tf32(v.z); v.w = rna_tf32(v.w);
    out[i] = v;
}

__global__ void prep_wfab(const float4* __restrict__ wfa, const float4* __restrict__ wga,
                          const float4* __restrict__ wb, float4* __restrict__ out, int total4) {
    const int i = blockIdx.x * 256 + threadIdx.x;
    if (i >= total4) return;
    const int n4 = i % (NFAB / 4);
    const int row = i / (NFAB / 4);
    float4 v = make_float4(0.f, 0.f, 0.f, 0.f);
    if (n4 < 32)       v = wfa[row * 32 + n4];
    else if (n4 < 64)  v = wga[row * 32 + (n4 - 32)];
    else if (n4 < 72)  v = wb[row * 8 + (n4 - 64)];
    v.x = rna_tf32(v.x); v.y = rna_tf32(v.y);
    v.z = rna_tf32(v.z); v.w = rna_tf32(v.w);
    out[i] = v;
}

// ---------------- conv / beta / gate (R11 exact) --------------------------------
__global__ __launch_bounds__(256) void conv_silu_k(const float* __restrict__ x,
                                                   const float* __restrict__ w,
                                                   float* __restrict__ y, float scale) {
    const int idx = blockIdx.x * 256 + threadIdx.x;
    const int t = idx >> 12;
    const int p = idx & (PP - 1);
    const size_t xi = (size_t)t * NQKV + p;
    const float4 wv = *reinterpret_cast<const float4*>(w + p * 4);
    float acc = x[xi] * wv.w;
    if (t >= 1) acc += x[xi - NQKV] * wv.z;
    if (t >= 2) acc += x[xi - 2 * NQKV] * wv.y;
    if (t >= 3) acc += x[xi - 3 * NQKV] * wv.x;
    const float sg = 1.f / (1.f + expf(-acc));
    y[idx] = acc * sg * scale;
}

__global__ void beta_k(const float* __restrict__ fab, float* __restrict__ b) {
    const int idx = blockIdx.x * 256 + threadIdx.x;
    if (idx >= TT * NH) return;
    const int t = idx >> 5, h = idx & 31;
    const float x = fab[(size_t)t * NFAB + 256 + h];
    b[idx] = 2.f / (1.f + expf(-x));
}

__global__ __launch_bounds__(256) void gate_k(float* __restrict__ g,
                                              const float* __restrict__ dt_bias,
                                              const float* __restrict__ A_log) {
    const int idx = blockIdx.x * 256 + threadIdx.x;
    const int p = idx & (PP - 1);
    const int h = p >> 7;
    const float a = expf(A_log[h]);
    const float x = g[idx] + dt_bias[p];
    const float sg = 1.f / (1.f + expf(-a * x));
    g[idx] = expf(-5.f * sg);
}

// ---------------- KDA scan v6: R11 layout + f32x2 + pipelined output reduction -
// CTA = (jblock, head), 1024 threads: jl = tid>>5 (column), s = tid&31 (4 els).
// Step t's output reduction (5 shfl + store) is deferred and interleaved with
// step t+1's critical path so the two shfl chains overlap in the MIO pipe.
#define SBLK 8
#define SLOT_F 420                // k128|q128|e128|v32|beta1|pad3
#define BUF_F (SBLK * SLOT_F)
#define SNBUF 3
#define NBLK (TT / SBLK)

__global__ __launch_bounds__(1024) void scan_k(const float* __restrict__ q,
                                               const float* __restrict__ k,
                                               const float* __restrict__ v,
                                               const float* __restrict__ eg,
                                               const float* __restrict__ beta,
                                               float* __restrict__ o) {
    __shared__ __align__(16) float ring[SNBUF * BUF_F];   // 40.3KB

    const int tid = threadIdx.x;
    const int h = blockIdx.y;
    const int jb = blockIdx.x;              // 0..3
    const int jl = tid >> 5;                // column within block (0..31)
    const int s = tid & 31;                 // state slice (0..31), 4 els each
    const int off_v = h * HD + jb * 32 + jl;
    const uint32_t ring_u32 = smem_u32(ring);

    const float* kqe_base[3] = {k + h * HD, q + h * HD, eg + h * HD};

#define SCAN_FILL(blk) do {                                                     \
        const int t0 = (blk) * SBLK;                                            \
        const uint32_t bufb = ring_u32 + ((blk) % SNBUF) * (BUF_F * 4);         \
        if (tid < SBLK * 104) {                                                 \
            const int st = tid / 104;                                           \
            const int item = tid - st * 104;                                    \
            const size_t gbase = (size_t)(t0 + st) * PP;                        \
            const float* src;                                                   \
            if (item < 96) src = kqe_base[item >> 5] + gbase + (item & 31) * 4; \
            else           src = v + gbase + h * HD + jb * 32 + (item - 96) * 4;\
            cp_async16(bufb + (st * SLOT_F + item * 4) * 4, src);               \
        }                                                                       \
        if (tid < SBLK)                                                         \
            cp_async4(bufb + (tid * SLOT_F + 416) * 4,                          \
                      beta + (size_t)(t0 + tid) * NH + h);                      \
        cp_commit();                                                            \
    } while (0)

    u64t S01 = 0, S23 = 0;           // packed state {s0,s1},{s2,s3}
    const u64t Z2 = 0;
    float po_pend = 0.f;             // deferred output partial for step t-1

    SCAN_FILL(0);
    SCAN_FILL(1);

    for (int b = 0; b < NBLK; b++) {
        if (b < NBLK - 1) asm volatile("cp.async.wait_group 1;\n" ::: "memory");
        else              asm volatile("cp.async.wait_group 0;\n" ::: "memory");
        __syncthreads();
        if (b + 2 < NBLK) SCAN_FILL(b + 2);

        const float* buf = ring + (b % SNBUF) * BUF_F;
#pragma unroll
        for (int si = 0; si < SBLK; si++) {
            const int tg = b * SBLK + si;
            const float* slot = buf + si * SLOT_F;
            const ulonglong2 kk = *reinterpret_cast<const ulonglong2*>(slot + s * 4);
            const ulonglong2 qq = *reinterpret_cast<const ulonglong2*>(slot + 128 + s * 4);
            const ulonglong2 ee = *reinterpret_cast<const ulonglong2*>(slot + 256 + s * 4);
            const float vt = slot[384 + jl];
            const float bt = slot[416];

            // critical path: decay + key dot (packed)
            MUL2(S01, S01, ee.x);
            MUL2(S23, S23, ee.y);
            u64t p2;
            FMA2(p2, S01, kk.x, Z2);
            FMA2(p2, S23, kk.y, p2);
            float pl, ph; upk2(pl, ph, p2);
            float part = pl + ph;

            // flush previous step's output reduction (independent chain —
            // ptxas interleaves these shfls with the part-chain below)
            float pp = po_pend;
            pp += __shfl_xor_sync(0xffffffffu, pp, 1);
            pp += __shfl_xor_sync(0xffffffffu, pp, 2);
            pp += __shfl_xor_sync(0xffffffffu, pp, 4);
            pp += __shfl_xor_sync(0xffffffffu, pp, 8);
            pp += __shfl_xor_sync(0xffffffffu, pp, 16);

            part += __shfl_xor_sync(0xffffffffu, part, 1);
            part += __shfl_xor_sync(0xffffffffu, part, 2);
            part += __shfl_xor_sync(0xffffffffu, part, 4);
            part += __shfl_xor_sync(0xffffffffu, part, 8);
            part += __shfl_xor_sync(0xffffffffu, part, 16);

            if (s == 0 && tg > 0)
                o[(size_t)(tg - 1) * PP + off_v] = pp;

            const float u = bt * (vt - part);
            const u64t u2 = pk2(u, u);
            FMA2(S01, kk.x, u2, S01);
            FMA2(S23, kk.y, u2, S23);
            u64t o2;
            FMA2(o2, qq.x, S01, Z2);
            FMA2(o2, qq.y, S23, o2);
            float ol, oh; upk2(ol, oh, o2);
            po_pend = ol + oh;
        }
        __syncthreads();
    }

    // final pending output (t = TT-1)
    float pp = po_pend;
    pp += __shfl_xor_sync(0xffffffffu, pp, 1);
    pp += __shfl_xor_sync(0xffffffffu, pp, 2);
    pp += __shfl_xor_sync(0xffffffffu, pp, 4);
    pp += __shfl_xor_sync(0xffffffffu, pp, 8);
    pp += __shfl_xor_sync(0xffffffffu, pp, 16);
    if (s == 0)
        o[(size_t)(TT - 1) * PP + off_v] = pp;
}

// ---------------- gated RMSNorm (R11 exact) -------------------------------------
__global__ __launch_bounds__(256) void rmsnorm_k(float* __restrict__ o,
                                                 const float* __restrict__ g2,
                                                 const float* __restrict__ w) {
    const int warp = (blockIdx.x * blockDim.x + threadIdx.x) >> 5;
    const int lane = threadIdx.x & 31;
    if (warp >= TT * NH) return;
    const int base = warp * HD + lane * 4;
    float4 x = *reinterpret_cast<const float4*>(o + base);
    float ss = x.x * x.x + x.y * x.y + x.z * x.z + x.w * x.w;
#pragma unroll
    for (int d = 16; d > 0; d >>= 1) ss += __shfl_xor_sync(0xffffffffu, ss, d);
    const float rstd = rsqrtf(ss * (1.f / 128.f) + 1e-5f);
    const float4 g = *reinterpret_cast<const float4*>(g2 + base);
    const float4 wv = *reinterpret_cast<const float4*>(w + lane * 4);
    float4 r;
    r.x = rna_tf32(x.x * rstd * wv.x / (1.f + expf(-g.x)));
    r.y = rna_tf32(x.y * rstd * wv.y / (1.f + expf(-g.y)));
    r.z = rna_tf32(x.z * rstd * wv.z / (1.f + expf(-g.z)));
    r.w = rna_tf32(x.w * rstd * wv.w / (1.f + expf(-g.w)));
    *reinterpret_cast<float4*>(o + base) = r;
}

// ---------------- launch --------------------------------------------------------
extern "C" void kernel_launch(void* const* d_in, const int* in_sizes, int n_in,
                              void* d_out, int out_size) {
    const float* hs   = (const float*)d_in[0];
    const float* Wq   = (const float*)d_in[1];
    const float* Wk   = (const float*)d_in[2];
    const float* Wv   = (const float*)d_in[3];
    const float* cq   = (const float*)d_in[4];
    const float* ck   = (const float*)d_in[5];
    const float* cv   = (const float*)d_in[6];
    const float* Wb   = (const float*)d_in[7];
    const float* Wfa  = (const float*)d_in[8];
    const float* Wfb  = (const float*)d_in[9];
    const float* dtb  = (const float*)d_in[10];
    const float* Alog = (const float*)d_in[11];
    const float* Wga  = (const float*)d_in[12];
    const float* Wgb  = (const float*)d_in[13];
    const float* onw  = (const float*)d_in[14];
    const float* Wo   = (const float*)d_in[15];
    float* out = (float*)d_out;

    float *hsr, *qkvp, *q, *k, *v, *eg, *g2, *o, *fab, *beta;
    float *wqkvR, *wfabR, *wfbR, *wgbR, *woR;
    cudaGetSymbolAddress((void**)&hsr, g_hsr);
    cudaGetSymbolAddress((void**)&qkvp, g_qkvp);
    cudaGetSymbolAddress((void**)&q,  g_q);
    cudaGetSymbolAddress((void**)&k,  g_k);
    cudaGetSymbolAddress((void**)&v,  g_v);
    cudaGetSymbolAddress((void**)&eg, g_eg);
    cudaGetSymbolAddress((void**)&g2, g_g2);
    cudaGetSymbolAddress((void**)&o,  g_o);
    cudaGetSymbolAddress((void**)&fab, g_fab);
    cudaGetSymbolAddress((void**)&beta, g_beta);
    cudaGetSymbolAddress((void**)&wqkvR, g_wqkvR);
    cudaGetSymbolAddress((void**)&wfabR, g_wfabR);
    cudaGetSymbolAddress((void**)&wfbR, g_wfbR);
    cudaGetSymbolAddress((void**)&wgbR, g_wgbR);
    cudaGetSymbolAddress((void**)&woR, g_woR);

    cudaFuncSetAttribute(mma_gemm, cudaFuncAttributeMaxDynamicSharedMemorySize, GEMM_SMEM);

    const dim3 blk(256);

    // preps
    prep_w4<<<(TT * HID / 4 + 255) / 256, blk>>>((const float4*)hs, (float4*)hsr, TT * HID / 4);
    prep_wqkv<<<(HID * NQKV / 4 + 255) / 256, blk>>>((const float4*)Wq, (const float4*)Wk,
                                                     (const float4*)Wv, (float4*)wqkvR,
                                                     HID * NQKV / 4);
    prep_wfab<<<(HID * NFAB / 4 + 255) / 256, blk>>>((const float4*)Wfa, (const float4*)Wga,
                                                     (const float4*)Wb, (float4*)wfabR,
                                                     HID * NFAB / 4);

    // GEMMs
    mma_gemm<<<dim3(48, 32), blk, GEMM_SMEM>>>(hsr, HID, wqkvR, NQKV, qkvp, NQKV,
                                               NQKV / 2, HID, 0);
    mma_gemm<<<dim3(48, 32), blk, GEMM_SMEM>>>(hsr, HID, wqkvR + NQKV / 2, NQKV,
                                               qkvp + NQKV / 2, NQKV, NQKV / 2, HID, 0);
    mma_gemm<<<dim3(3, 32), blk, GEMM_SMEM>>>(hsr, HID, wfabR, NFAB, fab, NFAB,
                                              288, HID, 256);

    // convs + beta
    conv_silu_k<<<TP / 256, blk>>>(qkvp,          cq, q, 0.08838834764831845f);
    conv_silu_k<<<TP / 256, blk>>>(qkvp + PP,     ck, k, 1.f);
    conv_silu_k<<<TP / 256, blk>>>(qkvp + 2 * PP, cv, v, 1.f);
    beta_k<<<(TT * NH + 255) / 256, blk>>>(fab, beta);

    // gate GEMMs
    prep_w4<<<(HD * PP / 4 + 255) / 256, blk>>>((const float4*)Wfb, (float4*)wfbR, HD * PP / 4);
    mma_gemm<<<dim3(32, 32), blk, GEMM_SMEM>>>(fab, NFAB, wfbR, PP, eg, PP, PP, HD, 0);
    gate_k<<<TP / 256, blk>>>(eg, dtb, Alog);
    prep_w4<<<(HD * PP / 4 + 255) / 256, blk>>>((const float4*)Wgb, (float4*)wgbR, HD * PP / 4);
    mma_gemm<<<dim3(32, 32), blk, GEMM_SMEM>>>(fab + 128, NFAB, wgbR, PP, g2, PP, PP, HD, 0);

    // sequential KDA scan (v6: f32x2 + pipelined output reduction)
    scan_k<<<dim3(4, NH), 1024>>>(q, k, v, eg, beta, o);

    // gated rmsnorm + output projection
    rmsnorm_k<<<(TT * NH * 32) / 256, blk>>>(o, g2, onw);
    prep_w4<<<(PP * HID / 4 + 255) / 256, blk>>>((const float4*)Wo, (float4*)woR, PP * HID / 4);
    mma_gemm<<<dim3(16, 32), blk, GEMM_SMEM>>>(o, PP, woR, HID, out, HID, HID, PP, 0);
}

// round 14
// speedup vs baseline: 1.4851x; 1.0525x over previous
#include <cuda_runtime.h>
#include <math.h>
#include <stdint.h>

#define TT   4096
#define HID  2048
#define NH   32
#define HD   128
#define PP   4096
#define TP   (TT * PP)
#define NQKV 12288    // 3*PP
#define NFAB 384      // fa(128) | ga(128) | beta(32 pad->128)

// ---------------- scratch (device globals; no allocations allowed) ----------
__device__ float g_hsr[TT * HID];
__device__ float g_qkvp[TT * NQKV];
__device__ float g_q [TP];
__device__ float g_k [TP];
__device__ float g_v [TP];
__device__ float g_eg[TP];
__device__ float g_g2[TP];
__device__ float g_o [TP];
__device__ float g_fab[TT * NFAB];
__device__ float g_beta[TT * NH];
__device__ float g_wqkvR[HID * NQKV];
__device__ float g_wfabR[HID * NFAB];
__device__ float g_wfbR[HD * PP];
__device__ float g_wgbR[HD * PP];
__device__ float g_woR[PP * HID];

// ---------------- helpers -----------------------------------------------------
__device__ __forceinline__ uint32_t smem_u32(const void* p) {
    uint32_t a;
    asm("{ .reg .u64 t; cvta.to.shared.u64 t, %1; cvt.u32.u64 %0, t; }" : "=r"(a) : "l"(p));
    return a;
}
__device__ __forceinline__ float rna_tf32(float x) {
    uint32_t o, i = __float_as_uint(x);
    asm("cvt.rna.tf32.f32 %0, %1;" : "=r"(o) : "r"(i));
    return __uint_as_float(o);
}
__device__ __forceinline__ void cp_async16(uint32_t dst, const float* src) {
    asm volatile("cp.async.cg.shared.global [%0], [%1], 16;\n"
                 :: "r"(dst), "l"(__cvta_generic_to_global(src)));
}
__device__ __forceinline__ void cp_async4(uint32_t dst, const float* src) {
    asm volatile("cp.async.ca.shared.global [%0], [%1], 4;\n"
                 :: "r"(dst), "l"(__cvta_generic_to_global(src)));
}
__device__ __forceinline__ void cp_commit() { asm volatile("cp.async.commit_group;\n" ::: "memory"); }

#define MMA_TF32(d, a, b)                                                      \
    asm volatile("mma.sync.aligned.m16n8k8.row.col.f32.tf32.tf32.f32 "        \
                 "{%0,%1,%2,%3}, {%4,%5,%6,%7}, {%8,%9}, {%0,%1,%2,%3};"      \
                 : "+f"((d)[0]), "+f"((d)[1]), "+f"((d)[2]), "+f"((d)[3])     \
                 : "r"((a)[0]), "r"((a)[1]), "r"((a)[2]), "r"((a)[3]),        \
                   "r"((b)[0]), "r"((b)[1]))

#define LDSM_X4(r, addr)                                                       \
    asm volatile("ldmatrix.sync.aligned.m8n8.x4.shared.b16 {%0,%1,%2,%3}, [%4];" \
                 : "=r"((r)[0]), "=r"((r)[1]), "=r"((r)[2]), "=r"((r)[3])      \
                 : "r"(addr))

// packed f32x2 ops (base sm_100+ PTX)
typedef unsigned long long u64t;
#define FMA2(d, a, b, c) asm("fma.rn.f32x2 %0, %1, %2, %3;" : "=l"(d) : "l"(a), "l"(b), "l"(c))
#define MUL2(d, a, b)    asm("mul.rn.f32x2 %0, %1, %2;"     : "=l"(d) : "l"(a), "l"(b))
__device__ __forceinline__ u64t pk2(float lo, float hi) {
    u64t r; asm("mov.b64 %0, {%1, %2};" : "=l"(r) : "f"(lo), "f"(hi)); return r;
}
__device__ __forceinline__ void upk2(float& lo, float& hi, u64t v) {
    asm("mov.b64 {%0, %1}, %2;" : "=f"(lo), "=f"(hi) : "l"(v));
}

// ---------------- tf32 mma.sync GEMM (R8/R11/R13 exact) ------------------------
#define BM 128
#define BN 128
#define BK 32
#define ASTR 36
#define BSTR 136
#define A_STAGE (BM * ASTR)
#define B_STAGE (BK * BSTR)
#define STAGE_F (A_STAGE + B_STAGE)
#define NSTAGE 3
#define GEMM_SMEM (NSTAGE * STAGE_F * 4)

__global__ __launch_bounds__(256, 2) void mma_gemm(const float* __restrict__ A, int lda,
                                                   const float* __restrict__ B, int ldb,
                                                   float* __restrict__ C, int ldc,
                                                   int Nvalid, int K, int round_limit) {
    extern __shared__ float sm[];
    const uint32_t sb = smem_u32(sm);

    const int tid = threadIdx.x;
    const int wid = tid >> 5, lane = tid & 31;
    const int g = lane >> 2, tig = lane & 3;
    const int wm = (wid & 1) * 64, wn = (wid >> 1) * 32;
    const int bm = blockIdx.y * BM, bn = blockIdx.x * BN;
    const int NC = K >> 5;

    const int arow = tid >> 3, akq = tid & 7;
    const int brow = tid >> 5, bnq = tid & 31;
    const int aoff = (wm + (lane & 7) + ((lane >> 3) & 1) * 8) * ASTR + (lane >> 4) * 4;

    float acc[4][4][4];
#pragma unroll
    for (int i = 0; i < 4; i++)
#pragma unroll
        for (int j = 0; j < 4; j++)
#pragma unroll
            for (int r = 0; r < 4; r++) acc[i][j][r] = 0.f;

#define LOADST(chunk, stage) do {                                               \
        const int kb = (chunk) * BK;                                            \
        const uint32_t sA = sb + (stage) * STAGE_F * 4;                         \
        const uint32_t sB = sA + A_STAGE * 4;                                   \
        _Pragma("unroll")                                                       \
        for (int j = 0; j < 4; j++) {                                           \
            const int r = arow + 32 * j;                                        \
            cp_async16(sA + (r * ASTR + akq * 4) * 4,                           \
                       A + (size_t)(bm + r) * lda + kb + akq * 4);              \
        }                                                                       \
        _Pragma("unroll")                                                       \
        for (int j = 0; j < 4; j++) {                                           \
            const int r = brow + 8 * j;                                         \
            cp_async16(sB + (r * BSTR + bnq * 4) * 4,                           \
                       B + (size_t)(kb + r) * ldb + bn + bnq * 4);              \
        }                                                                       \
        cp_commit();                                                            \
    } while (0)

    LOADST(0, 0);
    if (NC > 1) LOADST(1, 1);

    for (int i = 0; i < NC; i++) {
        if (i + 2 < NC) asm volatile("cp.async.wait_group 1;\n" ::: "memory");
        else            asm volatile("cp.async.wait_group 0;\n" ::: "memory");
        __syncthreads();
        if (i + 2 < NC) {
            int st = i + 2;
            st = st - (st / NSTAGE) * NSTAGE;
            LOADST(i + 2, st);
        }

        const int stage = i - (i / NSTAGE) * NSTAGE;
        const uint32_t aBase = sb + stage * (STAGE_F * 4);
        const float* bb = sm + stage * STAGE_F + A_STAGE;
#pragma unroll
        for (int s = 0; s < 4; s++) {
            uint32_t af[4][4], bf[4][2];
            const int kk = 8 * s + tig;
#pragma unroll
            for (int mf = 0; mf < 4; mf++)
                LDSM_X4(af[mf], aBase + (uint32_t)(aoff + mf * (16 * ASTR) + 8 * s) * 4);
            const float* brow0 = bb + kk * BSTR + wn;
#pragma unroll
            for (int nf = 0; nf < 4; nf++) {
                bf[nf][0] = __float_as_uint(brow0[8 * nf + g]);
                bf[nf][1] = __float_as_uint(brow0[8 * nf + g + 4 * BSTR]);
            }
#pragma unroll
            for (int mf = 0; mf < 4; mf++)
#pragma unroll
                for (int nf = 0; nf < 4; nf++)
                    MMA_TF32(acc[mf][nf], af[mf], bf[nf]);
        }
    }

#pragma unroll
    for (int mf = 0; mf < 4; mf++) {
        const int row0 = bm + wm + 16 * mf + g;
#pragma unroll
        for (int nf = 0; nf < 4; nf++) {
            const int col = bn + wn + 8 * nf + 2 * tig;
            if (col < Nvalid) {
                float4 vals = make_float4(acc[mf][nf][0], acc[mf][nf][1],
                                          acc[mf][nf][2], acc[mf][nf][3]);
                if (col < round_limit) {
                    vals.x = rna_tf32(vals.x); vals.y = rna_tf32(vals.y);
                    vals.z = rna_tf32(vals.z); vals.w = rna_tf32(vals.w);
                }
                *reinterpret_cast<float2*>(C + (size_t)row0 * ldc + col) =
                    make_float2(vals.x, vals.y);
                *reinterpret_cast<float2*>(C + (size_t)(row0 + 8) * ldc + col) =
                    make_float2(vals.z, vals.w);
            }
        }
    }
}

// ---------------- prep kernels (R13 exact) --------------------------------------
__global__ void prep_w4(const float4* __restrict__ in, float4* __restrict__ out, int n4) {
    const int i = blockIdx.x * 256 + threadIdx.x;
    if (i >= n4) return;
    float4 v = in[i];
    v.x = rna_tf32(v.x); v.y = rna_tf32(v.y);
    v.z = rna_tf32(v.z); v.w = rna_tf32(v.w);
    out[i] = v;
}

__global__ void prep_wqkv(const float4* __restrict__ wq, const float4* __restrict__ wk,
                          const float4* __restrict__ wv, float4* __restrict__ out, int total4) {
    const int i = blockIdx.x * 256 + threadIdx.x;
    if (i >= total4) return;
    const int n4 = i % (NQKV / 4);
    const int row = i / (NQKV / 4);
    const int seg = n4 >> 10;
    const int off = row * (PP / 4) + (n4 & 1023);
    float4 v = (seg == 0) ? wq[off] : (seg == 1) ? wk[off] : wv[off];
    v.x = rna_tf32(v.x); v.y = rna_tf32(v.y);
    v.z = rna_tf32(v.z); v.w = rna_tf32(v.w);
    out[i] = v;
}

__global__ void prep_wfab(const float4* __restrict__ wfa, const float4* __restrict__ wga,
                          const float4* __restrict__ wb, float4* __restrict__ out, int total4) {
    const int i = blockIdx.x * 256 + threadIdx.x;
    if (i >= total4) return;
    const int n4 = i % (NFAB / 4);
    const int row = i / (NFAB / 4);
    float4 v = make_float4(0.f, 0.f, 0.f, 0.f);
    if (n4 < 32)       v = wfa[row * 32 + n4];
    else if (n4 < 64)  v = wga[row * 32 + (n4 - 32)];
    else if (n4 < 72)  v = wb[row * 8 + (n4 - 64)];
    v.x = rna_tf32(v.x); v.y = rna_tf32(v.y);
    v.z = rna_tf32(v.z); v.w = rna_tf32(v.w);
    out[i] = v;
}

// ---------------- conv / beta / gate (R13 exact) --------------------------------
__global__ __launch_bounds__(256) void conv_silu_k(const float* __restrict__ x,
                                                   const float* __restrict__ w,
                                                   float* __restrict__ y, float scale) {
    const int idx = blockIdx.x * 256 + threadIdx.x;
    const int t = idx >> 12;
    const int p = idx & (PP - 1);
    const size_t xi = (size_t)t * NQKV + p;
    const float4 wv = *reinterpret_cast<const float4*>(w + p * 4);
    float acc = x[xi] * wv.w;
    if (t >= 1) acc += x[xi - NQKV] * wv.z;
    if (t >= 2) acc += x[xi - 2 * NQKV] * wv.y;
    if (t >= 3) acc += x[xi - 3 * NQKV] * wv.x;
    const float sg = 1.f / (1.f + expf(-acc));
    y[idx] = acc * sg * scale;
}

__global__ void beta_k(const float* __restrict__ fab, float* __restrict__ b) {
    const int idx = blockIdx.x * 256 + threadIdx.x;
    if (idx >= TT * NH) return;
    const int t = idx >> 5, h = idx & 31;
    const float x = fab[(size_t)t * NFAB + 256 + h];
    b[idx] = 2.f / (1.f + expf(-x));
}

__global__ __launch_bounds__(256) void gate_k(float* __restrict__ g,
                                              const float* __restrict__ dt_bias,
                                              const float* __restrict__ A_log) {
    const int idx = blockIdx.x * 256 + threadIdx.x;
    const int p = idx & (PP - 1);
    const int h = p >> 7;
    const float a = expf(A_log[h]);
    const float x = g[idx] + dt_bias[p];
    const float sg = 1.f / (1.f + expf(-a * x));
    g[idx] = expf(-5.f * sg);
}

// ---------------- KDA scan v7: output reduction via smem (no output shfl) ------
// CTA = (jblock, head), 1024 threads: jl = tid>>5 (column), s = tid&31 (4 els).
// Per step: only the part-reduction butterfly (5 shfl) remains; output partials
// go to smem and are reduced once per 8-step block by all 1024 threads.
#define SBLK 8
#define SLOT_F 420                // k128|q128|e128|v32|beta1|pad3
#define BUF_F (SBLK * SLOT_F)
#define SNBUF 3
#define NBLK (TT / SBLK)

__global__ __launch_bounds__(1024) void scan_k(const float* __restrict__ q,
                                               const float* __restrict__ k,
                                               const float* __restrict__ v,
                                               const float* __restrict__ eg,
                                               const float* __restrict__ beta,
                                               float* __restrict__ o) {
    __shared__ __align__(16) float ring[SNBUF * BUF_F];   // 40.3KB
    __shared__ __align__(16) float op[SBLK * 32 * 32];    // 32KB output partials

    const int tid = threadIdx.x;
    const int h = blockIdx.y;
    const int jb = blockIdx.x;              // 0..3
    const int jl = tid >> 5;                // column within block (0..31)
    const int s = tid & 31;                 // state slice (0..31), 4 els each
    const uint32_t ring_u32 = smem_u32(ring);

    // phase-B assignment: 4 threads per output
    const int outi = tid >> 2;              // 0..255
    const int prt = tid & 3;
    const int osi = outi >> 5;              // step within block
    const int ocol = outi & 31;             // column
    const size_t obase = (size_t)h * HD + jb * 32 + ocol;

    const float* kqe_base[3] = {k + h * HD, q + h * HD, eg + h * HD};

#define SCAN_FILL(blk) do {                                                     \
        const int t0 = (blk) * SBLK;                                            \
        const uint32_t bufb = ring_u32 + ((blk) % SNBUF) * (BUF_F * 4);         \
        if (tid < SBLK * 104) {                                                 \
            const int st = tid / 104;                                           \
            const int item = tid - st * 104;                                    \
            const size_t gbase = (size_t)(t0 + st) * PP;                        \
            const float* src;                                                   \
            if (item < 96) src = kqe_base[item >> 5] + gbase + (item & 31) * 4; \
            else           src = v + gbase + h * HD + jb * 32 + (item - 96) * 4;\
            cp_async16(bufb + (st * SLOT_F + item * 4) * 4, src);               \
        }                                                                       \
        if (tid < SBLK)                                                         \
            cp_async4(bufb + (tid * SLOT_F + 416) * 4,                          \
                      beta + (size_t)(t0 + tid) * NH + h);                      \
        cp_commit();                                                            \
    } while (0)

    u64t S01 = 0, S23 = 0;           // packed state {s0,s1},{s2,s3}
    const u64t Z2 = 0;

    SCAN_FILL(0);
    SCAN_FILL(1);

    for (int b = 0; b < NBLK; b++) {
        if (b < NBLK - 1) asm volatile("cp.async.wait_group 1;\n" ::: "memory");
        else              asm volatile("cp.async.wait_group 0;\n" ::: "memory");
        __syncthreads();
        if (b + 2 < NBLK) SCAN_FILL(b + 2);

        const float* buf = ring + (b % SNBUF) * BUF_F;
#pragma unroll
        for (int si = 0; si < SBLK; si++) {
            const float* slot = buf + si * SLOT_F;
            const ulonglong2 kk = *reinterpret_cast<const ulonglong2*>(slot + s * 4);
            const ulonglong2 qq = *reinterpret_cast<const ulonglong2*>(slot + 128 + s * 4);
            const ulonglong2 ee = *reinterpret_cast<const ulonglong2*>(slot + 256 + s * 4);
            const float vt = slot[384 + jl];
            const float bt = slot[416];

            // critical path: decay + key dot (packed)
            MUL2(S01, S01, ee.x);
            MUL2(S23, S23, ee.y);
            u64t p2;
            FMA2(p2, S01, kk.x, Z2);
            FMA2(p2, S23, kk.y, p2);
            float pl, ph; upk2(pl, ph, p2);
            float part = pl + ph;
            part += __shfl_xor_sync(0xffffffffu, part, 1);
            part += __shfl_xor_sync(0xffffffffu, part, 2);
            part += __shfl_xor_sync(0xffffffffu, part, 4);
            part += __shfl_xor_sync(0xffffffffu, part, 8);
            part += __shfl_xor_sync(0xffffffffu, part, 16);

            const float u = bt * (vt - part);
            const u64t u2 = pk2(u, u);
            FMA2(S01, kk.x, u2, S01);
            FMA2(S23, kk.y, u2, S23);
            u64t o2;
            FMA2(o2, qq.x, S01, Z2);
            FMA2(o2, qq.y, S23, o2);
            float ol, oh; upk2(ol, oh, o2);
            op[(si * 32 + jl) * 32 + s] = ol + oh;   // no shfl — defer to phase B
        }
        __syncthreads();

        // phase B: reduce 256 outputs (8 steps x 32 cols), 4 threads each
        {
            const float* src = op + (osi * 32 + ocol) * 32 + prt * 8;
            float4 x0 = *reinterpret_cast<const float4*>(src);
            float4 x1 = *reinterpret_cast<const float4*>(src + 4);
            float sum = ((x0.x + x0.y) + (x0.z + x0.w)) +
                        ((x1.x + x1.y) + (x1.z + x1.w));
            sum += __shfl_xor_sync(0xffffffffu, sum, 1);
            sum += __shfl_xor_sync(0xffffffffu, sum, 2);
            if (prt == 0)
                o[(size_t)(b * SBLK + osi) * PP + obase] = sum;
        }
    }
}

// ---------------- gated RMSNorm (R13 exact) -------------------------------------
__global__ __launch_bounds__(256) void rmsnorm_k(float* __restrict__ o,
                                                 const float* __restrict__ g2,
                                                 const float* __restrict__ w) {
    const int warp = (blockIdx.x * blockDim.x + threadIdx.x) >> 5;
    const int lane = threadIdx.x & 31;
    if (warp >= TT * NH) return;
    const int base = warp * HD + lane * 4;
    float4 x = *reinterpret_cast<const float4*>(o + base);
    float ss = x.x * x.x + x.y * x.y + x.z * x.z + x.w * x.w;
#pragma unroll
    for (int d = 16; d > 0; d >>= 1) ss += __shfl_xor_sync(0xffffffffu, ss, d);
    const float rstd = rsqrtf(ss * (1.f / 128.f) + 1e-5f);
    const float4 g = *reinterpret_cast<const float4*>(g2 + base);
    const float4 wv = *reinterpret_cast<const float4*>(w + lane * 4);
    float4 r;
    r.x = rna_tf32(x.x * rstd * wv.x / (1.f + expf(-g.x)));
    r.y = rna_tf32(x.y * rstd * wv.y / (1.f + expf(-g.y)));
    r.z = rna_tf32(x.z * rstd * wv.z / (1.f + expf(-g.z)));
    r.w = rna_tf32(x.w * rstd * wv.w / (1.f + expf(-g.w)));
    *reinterpret_cast<float4*>(o + base) = r;
}

// ---------------- launch --------------------------------------------------------
extern "C" void kernel_launch(void* const* d_in, const int* in_sizes, int n_in,
                              void* d_out, int out_size) {
    const float* hs   = (const float*)d_in[0];
    const float* Wq   = (const float*)d_in[1];
    const float* Wk   = (const float*)d_in[2];
    const float* Wv   = (const float*)d_in[3];
    const float* cq   = (const float*)d_in[4];
    const float* ck   = (const float*)d_in[5];
    const float* cv   = (const float*)d_in[6];
    const float* Wb   = (const float*)d_in[7];
    const float* Wfa  = (const float*)d_in[8];
    const float* Wfb  = (const float*)d_in[9];
    const float* dtb  = (const float*)d_in[10];
    const float* Alog = (const float*)d_in[11];
    const float* Wga  = (const float*)d_in[12];
    const float* Wgb  = (const float*)d_in[13];
    const float* onw  = (const float*)d_in[14];
    const float* Wo   = (const float*)d_in[15];
    float* out = (float*)d_out;

    float *hsr, *qkvp, *q, *k, *v, *eg, *g2, *o, *fab, *beta;
    float *wqkvR, *wfabR, *wfbR, *wgbR, *woR;
    cudaGetSymbolAddress((void**)&hsr, g_hsr);
    cudaGetSymbolAddress((void**)&qkvp, g_qkvp);
    cudaGetSymbolAddress((void**)&q,  g_q);
    cudaGetSymbolAddress((void**)&k,  g_k);
    cudaGetSymbolAddress((void**)&v,  g_v);
    cudaGetSymbolAddress((void**)&eg, g_eg);
    cudaGetSymbolAddress((void**)&g2, g_g2);
    cudaGetSymbolAddress((void**)&o,  g_o);
    cudaGetSymbolAddress((void**)&fab, g_fab);
    cudaGetSymbolAddress((void**)&beta, g_beta);
    cudaGetSymbolAddress((void**)&wqkvR, g_wqkvR);
    cudaGetSymbolAddress((void**)&wfabR, g_wfabR);
    cudaGetSymbolAddress((void**)&wfbR, g_wfbR);
    cudaGetSymbolAddress((void**)&wgbR, g_wgbR);
    cudaGetSymbolAddress((void**)&woR, g_woR);

    cudaFuncSetAttribute(mma_gemm, cudaFuncAttributeMaxDynamicSharedMemorySize, GEMM_SMEM);

    const dim3 blk(256);

    // preps
    prep_w4<<<(TT * HID / 4 + 255) / 256, blk>>>((const float4*)hs, (float4*)hsr, TT * HID / 4);
    prep_wqkv<<<(HID * NQKV / 4 + 255) / 256, blk>>>((const float4*)Wq, (const float4*)Wk,
                                                     (const float4*)Wv, (float4*)wqkvR,
                                                     HID * NQKV / 4);
    prep_wfab<<<(HID * NFAB / 4 + 255) / 256, blk>>>((const float4*)Wfa, (const float4*)Wga,
                                                     (const float4*)Wb, (float4*)wfabR,
                                                     HID * NFAB / 4);

    // GEMMs
    mma_gemm<<<dim3(48, 32), blk, GEMM_SMEM>>>(hsr, HID, wqkvR, NQKV, qkvp, NQKV,
                                               NQKV / 2, HID, 0);
    mma_gemm<<<dim3(48, 32), blk, GEMM_SMEM>>>(hsr, HID, wqkvR + NQKV / 2, NQKV,
                                               qkvp + NQKV / 2, NQKV, NQKV / 2, HID, 0);
    mma_gemm<<<dim3(3, 32), blk, GEMM_SMEM>>>(hsr, HID, wfabR, NFAB, fab, NFAB,
                                              288, HID, 256);

    // convs + beta
    conv_silu_k<<<TP / 256, blk>>>(qkvp,          cq, q, 0.08838834764831845f);
    conv_silu_k<<<TP / 256, blk>>>(qkvp + PP,     ck, k, 1.f);
    conv_silu_k<<<TP / 256, blk>>>(qkvp + 2 * PP, cv, v, 1.f);
    beta_k<<<(TT * NH + 255) / 256, blk>>>(fab, beta);

    // gate GEMMs
    prep_w4<<<(HD * PP / 4 + 255) / 256, blk>>>((const float4*)Wfb, (float4*)wfbR, HD * PP / 4);
    mma_gemm<<<dim3(32, 32), blk, GEMM_SMEM>>>(fab, NFAB, wfbR, PP, eg, PP, PP, HD, 0);
    gate_k<<<TP / 256, blk>>>(eg, dtb, Alog);
    prep_w4<<<(HD * PP / 4 + 255) / 256, blk>>>((const float4*)Wgb, (float4*)wgbR, HD * PP / 4);
    mma_gemm<<<dim3(32, 32), blk, GEMM_SMEM>>>(fab + 128, NFAB, wgbR, PP, g2, PP, PP, HD, 0);

    // sequential KDA scan (v7: smem output reduction)
    scan_k<<<dim3(4, NH), 1024>>>(q, k, v, eg, beta, o);

    // gated rmsnorm + output projection
    rmsnorm_k<<<(TT * NH * 32) / 256, blk>>>(o, g2, onw);
    prep_w4<<<(PP * HID / 4 + 255) / 256, blk>>>((const float4*)Wo, (float4*)woR, PP * HID / 4);
    mma_gemm<<<dim3(16, 32), blk, GEMM_SMEM>>>(o, PP, woR, HID, out, HID, HID, PP, 0);
}